// round 12
// baseline (speedup 1.0000x reference)
#include <cuda_runtime.h>
#include <math.h>
#include <stdint.h>

#define TBITS 19
#define TSIZE (1u << TBITS)
#define TMASK (TSIZE - 1u)
#define NLEV 16
#define BLOCKA 256
#define BLOCKB 128
#define CH 65536   // 4 chunks; 4 scratch buffers (no WAR within one pass)
#define NBUF 4
#define MAXCHUNKS 16

// scratch buffers: per (level l, slot k) a float2 plane of CH points
//   k=0: (F[2l], F[2l+1]) ; k=1: (Gx0,Gx1) ; k=2: (Gy0,Gy1) ; k=3: (Gz0,Gz1)
__device__ float2 g_scratch[NBUF][64 * CH];

// weights in constant memory: FFMA takes c[bank][ofs] operand directly (no LDS)
__constant__ float cW1[1024];
__constant__ float cW2[1024];

// Dot2 building block: s/c = running twoSum accumulator, e = product-error sum.
__device__ __forceinline__ void dot2_term(float a, float b,
                                          float& s, float& c, float& e)
{
    float p = a * b;
    e += fmaf(a, b, -p);         // exact FMA product error
    float t = s + p;             // twoSum(s, p)
    float z = t - s;
    c += (s - (t - z)) + (p - z);
    s = t;
}

__device__ __forceinline__ void stcs_f2(float2* p, float2 v)
{
    __stcs(p, v);
}
__device__ __forceinline__ float2 ldcs_f2(const float2* p)
{
    return __ldcs(p);
}

__device__ __forceinline__ float shY(int c, float x, float y, float z,
                                     float xx, float yy, float zz,
                                     float xy, float yz, float xz)
{
    switch (c) {
    case 0:  return 0.28209479177387814f;
    case 1:  return -0.4886025119029199f * y;
    case 2:  return  0.4886025119029199f * z;
    case 3:  return -0.4886025119029199f * x;
    case 4:  return  1.0925484305920792f * xy;
    case 5:  return -1.0925484305920792f * yz;
    case 6:  return  0.31539156525252005f * (2.f * zz - xx - yy);
    case 7:  return -1.0925484305920792f * xz;
    case 8:  return  0.5462742152960396f * (xx - yy);
    case 9:  return -0.5900435899266435f * y * (3.f * xx - yy);
    case 10: return  2.890611442640554f  * xy * z;
    case 11: return -0.4570457994644658f * y * (4.f * zz - xx - yy);
    case 12: return  0.3731763325901154f * z * (2.f * zz - 3.f * xx - 3.f * yy);
    case 13: return -0.4570457994644658f * x * (4.f * zz - xx - yy);
    case 14: return  1.445305721320277f  * z * (xx - yy);
    case 15: return -0.5900435899266435f * x * (xx - 3.f * yy);
    }
    return 0.f;
}

// ---------------- Kernel A: hash-grid gather, one (point, level) per thread ----
__global__ __launch_bounds__(BLOCKA)
void ngp_encode_kernel(const float* __restrict__ pos,
                       const float* __restrict__ table,
                       const float* __restrict__ aabb,
                       int baseN, int chunk, int buf)
{
    __shared__ float sres;
    const int l = blockIdx.y;
    if (threadIdx.x == 0) {
        // Replicate reference: s = exp((ln(4096)-ln(16))/15); res_l = f32(16 * s^l)
        double s = exp(0.36967849629863747);
        sres = (float)(16.0 * pow(s, (double)l));
    }
    __syncthreads();

    const int n = blockIdx.x * BLOCKA + threadIdx.x;
    if (n >= chunk) return;
    const int ng = baseN + n;

    float P0 = pos[3 * ng + 0], P1 = pos[3 * ng + 1], P2 = pos[3 * ng + 2];
    float a0 = aabb[0], a1 = aabb[1], a2 = aabb[2];
    float s0 = fmaxf(aabb[3] - a0, 1e-6f);
    float s1 = fmaxf(aabb[4] - a1, 1e-6f);
    float s2 = fmaxf(aabb[5] - a2, 1e-6f);
    float q0 = __fdiv_rn(P0 - a0, s0);
    float q1 = __fdiv_rn(P1 - a1, s1);
    float q2 = __fdiv_rn(P2 - a2, s2);
    float pn0 = fminf(fmaxf(q0, 0.f), 1.f);
    float pn1 = fminf(fmaxf(q1, 0.f), 1.f);
    float pn2 = fminf(fmaxf(q2, 0.f), 1.f);

    const float res = sres;
    float px = pn0 * res, py = pn1 * res, pz = pn2 * res;
    float fx = floorf(px), fy = floorf(py), fz = floorf(pz);
    float wx = px - fx, wy = py - fy, wz = pz - fz;
    unsigned ux = (unsigned)fx, uy = (unsigned)fy, uz = (unsigned)fz;
    unsigned hx0 = ux,                hx1 = ux + 1u;
    unsigned hy0 = uy * 2654435761u,  hy1 = (uy + 1u) * 2654435761u;
    unsigned hz0 = uz * 805459861u,   hz1 = (uz + 1u) * 805459861u;
    const float2* tab = ((const float2*)table) + (size_t)l * TSIZE;

    // batch all 8 gathers first (max MLP), then accumulate in the SAME order
    float2 fv[8];
    #pragma unroll
    for (int c = 0; c < 8; c++) {
        const int bx = (c >> 2) & 1, by = (c >> 1) & 1, bz = c & 1;
        unsigned hh = (bx ? hx1 : hx0) ^ (by ? hy1 : hy0) ^ (bz ? hz1 : hz0);
        fv[c] = __ldg(&tab[hh & TMASK]);
    }

    float f0a = 0.f, f0b = 0.f, f1a = 0.f, f1b = 0.f;
    float gx0a = 0.f, gx0b = 0.f, gx1a = 0.f, gx1b = 0.f;
    float gy0a = 0.f, gy0b = 0.f, gy1a = 0.f, gy1b = 0.f;
    float gz0a = 0.f, gz0b = 0.f, gz1a = 0.f, gz1b = 0.f;

    #pragma unroll
    for (int c = 0; c < 8; c++) {
        const int bx = (c >> 2) & 1, by = (c >> 1) & 1, bz = c & 1;
        float2 f = fv[c];
        float tx = bx ? wx : (1.f - wx);
        float ty = by ? wy : (1.f - wy);
        float tz = bz ? wz : (1.f - wz);
        float pyz = ty * tz;
        float pxz = tx * tz;
        float pxy = tx * ty;
        float wc  = tx * pyz;
        float sx = bx ? pyz : -pyz;
        float sy = by ? pxz : -pxz;
        float sz = bz ? pxy : -pxy;
        if (c & 1) {
            f0b = fmaf(f.x, wc, f0b);   f1b = fmaf(f.y, wc, f1b);
            gx0b = fmaf(f.x, sx, gx0b); gx1b = fmaf(f.y, sx, gx1b);
            gy0b = fmaf(f.x, sy, gy0b); gy1b = fmaf(f.y, sy, gy1b);
            gz0b = fmaf(f.x, sz, gz0b); gz1b = fmaf(f.y, sz, gz1b);
        } else {
            f0a = fmaf(f.x, wc, f0a);   f1a = fmaf(f.y, wc, f1a);
            gx0a = fmaf(f.x, sx, gx0a); gx1a = fmaf(f.y, sx, gx1a);
            gy0a = fmaf(f.x, sy, gy0a); gy1a = fmaf(f.y, sy, gy1a);
            gz0a = fmaf(f.x, sz, gz0a); gz1a = fmaf(f.y, sz, gz1a);
        }
    }

    // streaming stores: scratch is consume-once, keep it out of the hot L2 set
    float2* S = g_scratch[buf];
    stcs_f2(&S[(size_t)(l * 4 + 0) * CH + n], make_float2(f0a + f0b, f1a + f1b));
    stcs_f2(&S[(size_t)(l * 4 + 1) * CH + n], make_float2((gx0a + gx0b) * res, (gx1a + gx1b) * res));
    stcs_f2(&S[(size_t)(l * 4 + 2) * CH + n], make_float2((gy0a + gy0b) * res, (gy1a + gy1b) * res));
    stcs_f2(&S[(size_t)(l * 4 + 3) * CH + n], make_float2((gz0a + gz0b) * res, (gz1a + gz1b) * res));
}

// ---------------- Kernel B: MLP fwd + bwd + SH, const-mem weights ----
__global__ __launch_bounds__(BLOCKB, 5)
void ngp_mlp_kernel(const float* __restrict__ pos,
                    const float* __restrict__ rx,
                    const float* __restrict__ aabb,
                    const int*   __restrict__ degp,
                    float* __restrict__ out,
                    int baseN, int chunk, int N, int buf)
{
    __shared__ __align__(16) float sOut[BLOCKB * 39];

    const int tid = threadIdx.x;
    const int n = blockIdx.x * BLOCKB + tid;
    const int ng = baseN + n;
    const float C0f = 0.28209479177387814f;
    const float2* S = g_scratch[buf];

    if (n < chunk) {
        float P0 = pos[3 * ng + 0], P1 = pos[3 * ng + 1], P2 = pos[3 * ng + 2];
        float a0 = aabb[0], a1 = aabb[1], a2 = aabb[2];
        float s0 = fmaxf(aabb[3] - a0, 1e-6f);
        float s1 = fmaxf(aabb[4] - a1, 1e-6f);
        float s2 = fmaxf(aabb[5] - a2, 1e-6f);
        float q0 = __fdiv_rn(P0 - a0, s0);
        float q1 = __fdiv_rn(P1 - a1, s1);
        float q2 = __fdiv_rn(P2 - a2, s2);
        bool sel = (q0 >= 0.f) && (q0 <= 1.f) &&
                   (q1 >= 0.f) && (q1 <= 1.f) &&
                   (q2 >= 0.f) && (q2 <= 1.f);

        // ---- load F from scratch (coalesced float2, evict-first) ----
        float F[32];
        #pragma unroll
        for (int l = 0; l < NLEV; l++) {
            float2 fl = ldcs_f2(&S[(size_t)(l * 4 + 0) * CH + n]);
            F[2 * l] = fl.x; F[2 * l + 1] = fl.y;
        }

        // ---- MLP layer 1: h = relu(F @ W1), const-operand FFMA ----
        float h[32];
        #pragma unroll
        for (int j = 0; j < 32; j++) {
            float a0_ = 0.f, a1_ = 0.f, a2_ = 0.f, a3_ = 0.f;
            #pragma unroll
            for (int i = 0; i < 32; i += 4) {
                a0_ = fmaf(F[i],     cW1[(i)     * 32 + j], a0_);
                a1_ = fmaf(F[i + 1], cW1[(i + 1) * 32 + j], a1_);
                a2_ = fmaf(F[i + 2], cW1[(i + 2) * 32 + j], a2_);
                a3_ = fmaf(F[i + 3], cW1[(i + 3) * 32 + j], a3_);
            }
            h[j] = fmaxf((a0_ + a2_) + (a1_ + a3_), 0.f);
        }

        // ---- view direction + SH, layer 2 early (before backward) ----
        int deg = 3;
        if (degp) {
            int v = degp[0];
            if (v >= 0 && v <= 8) deg = v;
        }
        int nact = (deg + 1) * (deg + 1);
        float dx = rx[0] - P0, dy = rx[1] - P1, dz = rx[2] - P2;
        float dn = __fsqrt_rn(dx * dx + dy * dy + dz * dz);
        float dnc = fmaxf(dn, 1e-20f);
        float X = __fdiv_rn(dx, dnc), Y = __fdiv_rn(dy, dnc), Z = __fdiv_rn(dz, dnc);
        float xx = X * X, yy = Y * Y, zz = Z * Z;
        float xy = X * Y, yz = Y * Z, xz = X * Z;

        float* row = &sOut[tid * 39];
        float scat0 = 0.f, scat1 = 0.f;
        #pragma unroll
        for (int c = 0; c < 16; c++) {
            float v0a = 0.f, v0b = 0.f, v1a = 0.f, v1b = 0.f;
            #pragma unroll
            for (int j = 0; j < 32; j += 2) {
                v0a = fmaf(h[j],     cW2[(j)     * 32 + 2 * c],     v0a);
                v1a = fmaf(h[j],     cW2[(j)     * 32 + 2 * c + 1], v1a);
                v0b = fmaf(h[j + 1], cW2[(j + 1) * 32 + 2 * c],     v0b);
                v1b = fmaf(h[j + 1], cW2[(j + 1) * 32 + 2 * c + 1], v1b);
            }
            float v0 = v0a + v0b, v1 = v1a + v1b;
            float Yc = shY(c, X, Y, Z, xx, yy, zz, xy, yz, xz);
            if (c < nact) {
                scat0 = fmaf(Yc, v0, scat0);
                scat1 = fmaf(Yc, v1, scat1);
            }
            row[7 + 2 * c]     = sel ? v0 : 0.f;
            row[7 + 2 * c + 1] = sel ? v1 : 0.f;
        }
        row[2] = sel ? scat0 : 0.f;
        row[3] = sel ? scat1 : 0.f;

        // ---- dens: compensated f32 dot (Dot2 ~ fp64 accuracy, FFMA cost) ----
        float sd0 = 0.f, cd0 = 0.f, ed0 = 0.f;
        float sd1 = 0.f, cd1 = 0.f, ed1 = 0.f;
        #pragma unroll
        for (int j = 0; j < 32; j++) {
            dot2_term(h[j], cW2[j * 32 + 0], sd0, cd0, ed0);
            dot2_term(h[j], cW2[j * 32 + 1], sd1, cd1, ed1);
        }
        float dot0 = sd0 + (cd0 + ed0);
        float dot1 = sd1 + (cd1 + ed1);
        float dens0 = C0f * dot0, dens1 = C0f * dot1;
        row[0] = sel ? dens0 : 0.f;
        row[1] = sel ? dens1 : 0.f;

        // ---- backward: f32 div/sqrt (exact ops, no amplification) ----
        float rf = __fsqrt_rn(dens0 * dens0 + dens1 * dens1);
        float uf0 = 0.f, uf1 = 0.f;
        if (rf > 0.f) { uf0 = __fdiv_rn(dens0, rf); uf1 = __fdiv_rn(dens1, rf); }
        float cu0 = C0f * uf0, cu1 = C0f * uf1;

        float gj[32];
        #pragma unroll
        for (int j = 0; j < 32; j++) {
            float v = fmaf(cu0, cW2[j * 32 + 0], cu1 * cW2[j * 32 + 1]);
            gj[j] = (h[j] > 0.f) ? v : 0.f;
        }

        float df[32];
        #pragma unroll
        for (int i = 0; i < 32; i++) {
            float a0_ = 0.f, a1_ = 0.f, a2_ = 0.f, a3_ = 0.f;
            #pragma unroll
            for (int j = 0; j < 32; j += 4) {
                a0_ = fmaf(gj[j],     cW1[i * 32 + j],     a0_);
                a1_ = fmaf(gj[j + 1], cW1[i * 32 + j + 1], a1_);
                a2_ = fmaf(gj[j + 2], cW1[i * 32 + j + 2], a2_);
                a3_ = fmaf(gj[j + 3], cW1[i * 32 + j + 3], a3_);
            }
            df[i] = (a0_ + a2_) + (a1_ + a3_);
        }

        // ---- final gradient reduction: Dot2 f32, then f32 normalize ----
        float sx = 0.f, cx = 0.f, ex = 0.f;
        float sy = 0.f, cy = 0.f, ey = 0.f;
        float sz = 0.f, cz = 0.f, ez = 0.f;
        #pragma unroll
        for (int l = 0; l < NLEV; l++) {
            float d0 = df[2 * l], d1 = df[2 * l + 1];
            float2 gx = ldcs_f2(&S[(size_t)(l * 4 + 1) * CH + n]);
            float2 gy = ldcs_f2(&S[(size_t)(l * 4 + 2) * CH + n]);
            float2 gz = ldcs_f2(&S[(size_t)(l * 4 + 3) * CH + n]);
            dot2_term(d0, gx.x, sx, cx, ex);
            dot2_term(d1, gx.y, sx, cx, ex);
            dot2_term(d0, gy.x, sy, cy, ey);
            dot2_term(d1, gy.y, sy, cy, ey);
            dot2_term(d0, gz.x, sz, cz, ez);
            dot2_term(d1, gz.y, sz, cz, ez);
        }
        float gpx = sx + (cx + ex);
        float gpy = sy + (cy + ey);
        float gpz = sz + (cz + ez);

        float gw0 = __fdiv_rn(gpx, s0);
        float gw1 = __fdiv_rn(gpy, s1);
        float gw2 = __fdiv_rn(gpz, s2);
        float gn = __fsqrt_rn(gw0 * gw0 + gw1 * gw1 + gw2 * gw2);
        float gd = fmaxf(gn, 1e-20f);
        row[4] = sel ? __fdiv_rn(-gw0, gd) : 0.f;
        row[5] = sel ? __fdiv_rn(-gw1, gd) : 0.f;
        row[6] = sel ? __fdiv_rn(-gw2, gd) : 0.f;
    }

    __syncthreads();

    // ---- coalesced staged output ----
    int base = baseN + blockIdx.x * BLOCKB;
    int npts = N - base;
    if (npts >= BLOCKB) {
        const float4* s4 = (const float4*)sOut;
        float4* o4 = (float4*)(out + (size_t)base * 39);
        #pragma unroll 4
        for (int i = tid; i < (BLOCKB * 39) / 4; i += BLOCKB)
            o4[i] = s4[i];
    } else if (npts > 0) {
        for (int i = tid; i < npts * 39; i += BLOCKB)
            out[(size_t)base * 39 + i] = sOut[i];
    }
}

extern "C" void kernel_launch(void* const* d_in, const int* in_sizes, int n_in,
                              void* d_out, int out_size)
{
    const float* pos   = (const float*)d_in[0];
    const float* rx    = (const float*)d_in[1];
    const float* table = (const float*)d_in[2];
    const float* W1    = (const float*)d_in[3];
    const float* W2    = (const float*)d_in[4];
    const float* aabb  = (const float*)d_in[5];
    const int*   degp  = (n_in > 6) ? (const int*)d_in[6] : nullptr;

    int N = in_sizes[0] / 3;

    // one-time stream/event creation (host-side only; happens on the first,
    // non-captured correctness call)
    static cudaStream_t strA = nullptr, strB = nullptr;
    static cudaEvent_t evRoot = nullptr, evDone = nullptr;
    static cudaEvent_t evA[MAXCHUNKS], evB[MAXCHUNKS];
    if (!strA) {
        cudaStreamCreateWithFlags(&strA, cudaStreamNonBlocking);
        cudaStreamCreateWithFlags(&strB, cudaStreamNonBlocking);
        cudaEventCreateWithFlags(&evRoot, cudaEventDisableTiming);
        cudaEventCreateWithFlags(&evDone, cudaEventDisableTiming);
        for (int i = 0; i < MAXCHUNKS; i++) {
            cudaEventCreateWithFlags(&evA[i], cudaEventDisableTiming);
            cudaEventCreateWithFlags(&evB[i], cudaEventDisableTiming);
        }
    }

    // fork both worker streams from the caller's (default) stream
    cudaEventRecord(evRoot, 0);
    cudaStreamWaitEvent(strA, evRoot, 0);
    cudaStreamWaitEvent(strB, evRoot, 0);

    // upload weights to constant memory on stream B (B is the only consumer)
    cudaMemcpyToSymbolAsync(cW1, W1, 1024 * sizeof(float), 0,
                            cudaMemcpyDeviceToDevice, strB);
    cudaMemcpyToSymbolAsync(cW2, W2, 1024 * sizeof(float), 0,
                            cudaMemcpyDeviceToDevice, strB);

    int nchunks = (N + CH - 1) / CH;
    if (nchunks > MAXCHUNKS) nchunks = MAXCHUNKS;

    for (int i = 0; i < nchunks; i++) {
        int base = i * CH;
        int chunk = (N - base < CH) ? (N - base) : CH;
        int buf = i % NBUF;
        // WAR guard: before A rewrites buffer `buf`, B_{i-NBUF} must be done
        if (i >= NBUF)
            cudaStreamWaitEvent(strA, evB[i - NBUF], 0);
        dim3 gridA((chunk + BLOCKA - 1) / BLOCKA, NLEV);
        ngp_encode_kernel<<<gridA, BLOCKA, 0, strA>>>(pos, table, aabb,
                                                      base, chunk, buf);
        cudaEventRecord(evA[i], strA);
        cudaStreamWaitEvent(strB, evA[i], 0);
        int gridB = (chunk + BLOCKB - 1) / BLOCKB;
        ngp_mlp_kernel<<<gridB, BLOCKB, 0, strB>>>(pos, rx, aabb, degp,
                                                   (float*)d_out, base, chunk,
                                                   N, buf);
        cudaEventRecord(evB[i], strB);
    }

    // rejoin into the caller's stream
    cudaEventRecord(evDone, strB);
    cudaStreamWaitEvent(0, evDone, 0);
}

// round 13
// speedup vs baseline: 1.1952x; 1.1952x over previous
#include <cuda_runtime.h>
#include <math.h>
#include <stdint.h>

#define TBITS 19
#define TSIZE (1u << TBITS)
#define TMASK (TSIZE - 1u)
#define NLEV 16
#define BLOCKA 256
#define NPT 2              // points per thread in kernel A
#define BLOCKB 128
#define CH 131072          // 2 chunks; double-buffered scratch
#define MAXCHUNKS 8

// double-buffered scratch: per (level l, slot k) a float2 plane of CH points
//   k=0: (F[2l], F[2l+1]) ; k=1: (Gx0,Gx1) ; k=2: (Gy0,Gy1) ; k=3: (Gz0,Gz1)
__device__ float2 g_scratch[2][64 * CH];

// weights in constant memory: FFMA takes c[bank][ofs] operand directly (no LDS)
__constant__ float cW1[1024];
__constant__ float cW2[1024];

// Dot2 building block: s/c = running twoSum accumulator, e = product-error sum.
__device__ __forceinline__ void dot2_term(float a, float b,
                                          float& s, float& c, float& e)
{
    float p = a * b;
    e += fmaf(a, b, -p);         // exact FMA product error
    float t = s + p;             // twoSum(s, p)
    float z = t - s;
    c += (s - (t - z)) + (p - z);
    s = t;
}

__device__ __forceinline__ float shY(int c, float x, float y, float z,
                                     float xx, float yy, float zz,
                                     float xy, float yz, float xz)
{
    switch (c) {
    case 0:  return 0.28209479177387814f;
    case 1:  return -0.4886025119029199f * y;
    case 2:  return  0.4886025119029199f * z;
    case 3:  return -0.4886025119029199f * x;
    case 4:  return  1.0925484305920792f * xy;
    case 5:  return -1.0925484305920792f * yz;
    case 6:  return  0.31539156525252005f * (2.f * zz - xx - yy);
    case 7:  return -1.0925484305920792f * xz;
    case 8:  return  0.5462742152960396f * (xx - yy);
    case 9:  return -0.5900435899266435f * y * (3.f * xx - yy);
    case 10: return  2.890611442640554f  * xy * z;
    case 11: return -0.4570457994644658f * y * (4.f * zz - xx - yy);
    case 12: return  0.3731763325901154f * z * (2.f * zz - 3.f * xx - 3.f * yy);
    case 13: return -0.4570457994644658f * x * (4.f * zz - xx - yy);
    case 14: return  1.445305721320277f  * z * (xx - yy);
    case 15: return -0.5900435899266435f * x * (xx - 3.f * yy);
    }
    return 0.f;
}

// ---------------- Kernel A: hash-grid gather, NPT points x 1 level per thread
__global__ __launch_bounds__(BLOCKA)
void ngp_encode_kernel(const float* __restrict__ pos,
                       const float* __restrict__ table,
                       const float* __restrict__ aabb,
                       int baseN, int chunk, int buf)
{
    __shared__ float sres;
    const int l = blockIdx.y;
    if (threadIdx.x == 0) {
        // Replicate reference: s = exp((ln(4096)-ln(16))/15); res_l = f32(16 * s^l)
        double s = exp(0.36967849629863747);
        sres = (float)(16.0 * pow(s, (double)l));
    }
    __syncthreads();

    const float res = sres;
    const float2* tab = ((const float2*)table) + (size_t)l * TSIZE;
    float2* S = g_scratch[buf];

    float a0 = aabb[0], a1 = aabb[1], a2 = aabb[2];
    float s0 = fmaxf(aabb[3] - a0, 1e-6f);
    float s1 = fmaxf(aabb[4] - a1, 1e-6f);
    float s2 = fmaxf(aabb[5] - a2, 1e-6f);

    const int base = blockIdx.x * (BLOCKA * NPT) + threadIdx.x;

    // per-point state
    int   np[NPT];
    float wxp[NPT], wyp[NPT], wzp[NPT];
    unsigned hx0p[NPT], hx1p[NPT], hy0p[NPT], hy1p[NPT], hz0p[NPT], hz1p[NPT];
    bool valid[NPT];

    // front-end for both points (independent chains interleave)
    #pragma unroll
    for (int p = 0; p < NPT; p++) {
        int n = base + p * BLOCKA;
        np[p] = n;
        valid[p] = (n < chunk);
        if (!valid[p]) continue;
        int ng = baseN + n;
        float P0 = pos[3 * ng + 0], P1 = pos[3 * ng + 1], P2 = pos[3 * ng + 2];
        float q0 = __fdiv_rn(P0 - a0, s0);
        float q1 = __fdiv_rn(P1 - a1, s1);
        float q2 = __fdiv_rn(P2 - a2, s2);
        float pn0 = fminf(fmaxf(q0, 0.f), 1.f);
        float pn1 = fminf(fmaxf(q1, 0.f), 1.f);
        float pn2 = fminf(fmaxf(q2, 0.f), 1.f);
        float px = pn0 * res, py = pn1 * res, pz = pn2 * res;
        float fx = floorf(px), fy = floorf(py), fz = floorf(pz);
        wxp[p] = px - fx; wyp[p] = py - fy; wzp[p] = pz - fz;
        unsigned ux = (unsigned)fx, uy = (unsigned)fy, uz = (unsigned)fz;
        hx0p[p] = ux;               hx1p[p] = ux + 1u;
        hy0p[p] = uy * 2654435761u; hy1p[p] = (uy + 1u) * 2654435761u;
        hz0p[p] = uz * 805459861u;  hz1p[p] = (uz + 1u) * 805459861u;
    }

    // batch ALL gathers for both points (2x MLP)
    float2 fv[NPT][8];
    #pragma unroll
    for (int p = 0; p < NPT; p++) {
        if (!valid[p]) continue;
        #pragma unroll
        for (int c = 0; c < 8; c++) {
            const int bx = (c >> 2) & 1, by = (c >> 1) & 1, bz = c & 1;
            unsigned hh = (bx ? hx1p[p] : hx0p[p]) ^
                          (by ? hy1p[p] : hy0p[p]) ^
                          (bz ? hz1p[p] : hz0p[p]);
            fv[p][c] = __ldg(&tab[hh & TMASK]);
        }
    }

    // accumulate + store per point (identical fma order to R11)
    #pragma unroll
    for (int p = 0; p < NPT; p++) {
        if (!valid[p]) continue;
        float wx = wxp[p], wy = wyp[p], wz = wzp[p];

        float f0a = 0.f, f0b = 0.f, f1a = 0.f, f1b = 0.f;
        float gx0a = 0.f, gx0b = 0.f, gx1a = 0.f, gx1b = 0.f;
        float gy0a = 0.f, gy0b = 0.f, gy1a = 0.f, gy1b = 0.f;
        float gz0a = 0.f, gz0b = 0.f, gz1a = 0.f, gz1b = 0.f;

        #pragma unroll
        for (int c = 0; c < 8; c++) {
            const int bx = (c >> 2) & 1, by = (c >> 1) & 1, bz = c & 1;
            float2 f = fv[p][c];
            float tx = bx ? wx : (1.f - wx);
            float ty = by ? wy : (1.f - wy);
            float tz = bz ? wz : (1.f - wz);
            float pyz = ty * tz;
            float pxz = tx * tz;
            float pxy = tx * ty;
            float wc  = tx * pyz;
            float sx = bx ? pyz : -pyz;
            float sy = by ? pxz : -pxz;
            float sz = bz ? pxy : -pxy;
            if (c & 1) {
                f0b = fmaf(f.x, wc, f0b);   f1b = fmaf(f.y, wc, f1b);
                gx0b = fmaf(f.x, sx, gx0b); gx1b = fmaf(f.y, sx, gx1b);
                gy0b = fmaf(f.x, sy, gy0b); gy1b = fmaf(f.y, sy, gy1b);
                gz0b = fmaf(f.x, sz, gz0b); gz1b = fmaf(f.y, sz, gz1b);
            } else {
                f0a = fmaf(f.x, wc, f0a);   f1a = fmaf(f.y, wc, f1a);
                gx0a = fmaf(f.x, sx, gx0a); gx1a = fmaf(f.y, sx, gx1a);
                gy0a = fmaf(f.x, sy, gy0a); gy1a = fmaf(f.y, sy, gy1a);
                gz0a = fmaf(f.x, sz, gz0a); gz1a = fmaf(f.y, sz, gz1a);
            }
        }

        int n = np[p];
        S[(size_t)(l * 4 + 0) * CH + n] = make_float2(f0a + f0b, f1a + f1b);
        S[(size_t)(l * 4 + 1) * CH + n] = make_float2((gx0a + gx0b) * res, (gx1a + gx1b) * res);
        S[(size_t)(l * 4 + 2) * CH + n] = make_float2((gy0a + gy0b) * res, (gy1a + gy1b) * res);
        S[(size_t)(l * 4 + 3) * CH + n] = make_float2((gz0a + gz0b) * res, (gz1a + gz1b) * res);
    }
}

// ---------------- Kernel B: MLP fwd + bwd + SH, const-mem weights ----
__global__ __launch_bounds__(BLOCKB, 5)
void ngp_mlp_kernel(const float* __restrict__ pos,
                    const float* __restrict__ rx,
                    const float* __restrict__ aabb,
                    const int*   __restrict__ degp,
                    float* __restrict__ out,
                    int baseN, int chunk, int N, int buf)
{
    __shared__ __align__(16) float sOut[BLOCKB * 39];

    const int tid = threadIdx.x;
    const int n = blockIdx.x * BLOCKB + tid;
    const int ng = baseN + n;
    const float C0f = 0.28209479177387814f;
    const float2* S = g_scratch[buf];

    if (n < chunk) {
        float P0 = pos[3 * ng + 0], P1 = pos[3 * ng + 1], P2 = pos[3 * ng + 2];
        float a0 = aabb[0], a1 = aabb[1], a2 = aabb[2];
        float s0 = fmaxf(aabb[3] - a0, 1e-6f);
        float s1 = fmaxf(aabb[4] - a1, 1e-6f);
        float s2 = fmaxf(aabb[5] - a2, 1e-6f);
        float q0 = __fdiv_rn(P0 - a0, s0);
        float q1 = __fdiv_rn(P1 - a1, s1);
        float q2 = __fdiv_rn(P2 - a2, s2);
        bool sel = (q0 >= 0.f) && (q0 <= 1.f) &&
                   (q1 >= 0.f) && (q1 <= 1.f) &&
                   (q2 >= 0.f) && (q2 <= 1.f);

        // ---- load F from scratch (coalesced float2) ----
        float F[32];
        #pragma unroll
        for (int l = 0; l < NLEV; l++) {
            float2 fl = __ldg(&S[(size_t)(l * 4 + 0) * CH + n]);
            F[2 * l] = fl.x; F[2 * l + 1] = fl.y;
        }

        // ---- MLP layer 1: h = relu(F @ W1), const-operand FFMA ----
        float h[32];
        #pragma unroll
        for (int j = 0; j < 32; j++) {
            float a0_ = 0.f, a1_ = 0.f, a2_ = 0.f, a3_ = 0.f;
            #pragma unroll
            for (int i = 0; i < 32; i += 4) {
                a0_ = fmaf(F[i],     cW1[(i)     * 32 + j], a0_);
                a1_ = fmaf(F[i + 1], cW1[(i + 1) * 32 + j], a1_);
                a2_ = fmaf(F[i + 2], cW1[(i + 2) * 32 + j], a2_);
                a3_ = fmaf(F[i + 3], cW1[(i + 3) * 32 + j], a3_);
            }
            h[j] = fmaxf((a0_ + a2_) + (a1_ + a3_), 0.f);
        }

        // ---- view direction + SH, layer 2 early (before backward) ----
        int deg = 3;
        if (degp) {
            int v = degp[0];
            if (v >= 0 && v <= 8) deg = v;
        }
        int nact = (deg + 1) * (deg + 1);
        float dx = rx[0] - P0, dy = rx[1] - P1, dz = rx[2] - P2;
        float dn = __fsqrt_rn(dx * dx + dy * dy + dz * dz);
        float dnc = fmaxf(dn, 1e-20f);
        float X = __fdiv_rn(dx, dnc), Y = __fdiv_rn(dy, dnc), Z = __fdiv_rn(dz, dnc);
        float xx = X * X, yy = Y * Y, zz = Z * Z;
        float xy = X * Y, yz = Y * Z, xz = X * Z;

        float* row = &sOut[tid * 39];
        float scat0 = 0.f, scat1 = 0.f;
        #pragma unroll
        for (int c = 0; c < 16; c++) {
            float v0a = 0.f, v0b = 0.f, v1a = 0.f, v1b = 0.f;
            #pragma unroll
            for (int j = 0; j < 32; j += 2) {
                v0a = fmaf(h[j],     cW2[(j)     * 32 + 2 * c],     v0a);
                v1a = fmaf(h[j],     cW2[(j)     * 32 + 2 * c + 1], v1a);
                v0b = fmaf(h[j + 1], cW2[(j + 1) * 32 + 2 * c],     v0b);
                v1b = fmaf(h[j + 1], cW2[(j + 1) * 32 + 2 * c + 1], v1b);
            }
            float v0 = v0a + v0b, v1 = v1a + v1b;
            float Yc = shY(c, X, Y, Z, xx, yy, zz, xy, yz, xz);
            if (c < nact) {
                scat0 = fmaf(Yc, v0, scat0);
                scat1 = fmaf(Yc, v1, scat1);
            }
            row[7 + 2 * c]     = sel ? v0 : 0.f;
            row[7 + 2 * c + 1] = sel ? v1 : 0.f;
        }
        row[2] = sel ? scat0 : 0.f;
        row[3] = sel ? scat1 : 0.f;

        // ---- dens: compensated f32 dot (Dot2 ~ fp64 accuracy, FFMA cost) ----
        float sd0 = 0.f, cd0 = 0.f, ed0 = 0.f;
        float sd1 = 0.f, cd1 = 0.f, ed1 = 0.f;
        #pragma unroll
        for (int j = 0; j < 32; j++) {
            dot2_term(h[j], cW2[j * 32 + 0], sd0, cd0, ed0);
            dot2_term(h[j], cW2[j * 32 + 1], sd1, cd1, ed1);
        }
        float dot0 = sd0 + (cd0 + ed0);
        float dot1 = sd1 + (cd1 + ed1);
        float dens0 = C0f * dot0, dens1 = C0f * dot1;
        row[0] = sel ? dens0 : 0.f;
        row[1] = sel ? dens1 : 0.f;

        // ---- backward: f32 div/sqrt (exact ops, no amplification) ----
        float rf = __fsqrt_rn(dens0 * dens0 + dens1 * dens1);
        float uf0 = 0.f, uf1 = 0.f;
        if (rf > 0.f) { uf0 = __fdiv_rn(dens0, rf); uf1 = __fdiv_rn(dens1, rf); }
        float cu0 = C0f * uf0, cu1 = C0f * uf1;

        float gj[32];
        #pragma unroll
        for (int j = 0; j < 32; j++) {
            float v = fmaf(cu0, cW2[j * 32 + 0], cu1 * cW2[j * 32 + 1]);
            gj[j] = (h[j] > 0.f) ? v : 0.f;
        }

        float df[32];
        #pragma unroll
        for (int i = 0; i < 32; i++) {
            float a0_ = 0.f, a1_ = 0.f, a2_ = 0.f, a3_ = 0.f;
            #pragma unroll
            for (int j = 0; j < 32; j += 4) {
                a0_ = fmaf(gj[j],     cW1[i * 32 + j],     a0_);
                a1_ = fmaf(gj[j + 1], cW1[i * 32 + j + 1], a1_);
                a2_ = fmaf(gj[j + 2], cW1[i * 32 + j + 2], a2_);
                a3_ = fmaf(gj[j + 3], cW1[i * 32 + j + 3], a3_);
            }
            df[i] = (a0_ + a2_) + (a1_ + a3_);
        }

        // ---- final gradient reduction: Dot2 f32, then f32 normalize ----
        float sx = 0.f, cx = 0.f, ex = 0.f;
        float sy = 0.f, cy = 0.f, ey = 0.f;
        float sz = 0.f, cz = 0.f, ez = 0.f;
        #pragma unroll
        for (int l = 0; l < NLEV; l++) {
            float d0 = df[2 * l], d1 = df[2 * l + 1];
            float2 gx = __ldg(&S[(size_t)(l * 4 + 1) * CH + n]);
            float2 gy = __ldg(&S[(size_t)(l * 4 + 2) * CH + n]);
            float2 gz = __ldg(&S[(size_t)(l * 4 + 3) * CH + n]);
            dot2_term(d0, gx.x, sx, cx, ex);
            dot2_term(d1, gx.y, sx, cx, ex);
            dot2_term(d0, gy.x, sy, cy, ey);
            dot2_term(d1, gy.y, sy, cy, ey);
            dot2_term(d0, gz.x, sz, cz, ez);
            dot2_term(d1, gz.y, sz, cz, ez);
        }
        float gpx = sx + (cx + ex);
        float gpy = sy + (cy + ey);
        float gpz = sz + (cz + ez);

        float gw0 = __fdiv_rn(gpx, s0);
        float gw1 = __fdiv_rn(gpy, s1);
        float gw2 = __fdiv_rn(gpz, s2);
        float gn = __fsqrt_rn(gw0 * gw0 + gw1 * gw1 + gw2 * gw2);
        float gd = fmaxf(gn, 1e-20f);
        row[4] = sel ? __fdiv_rn(-gw0, gd) : 0.f;
        row[5] = sel ? __fdiv_rn(-gw1, gd) : 0.f;
        row[6] = sel ? __fdiv_rn(-gw2, gd) : 0.f;
    }

    __syncthreads();

    // ---- coalesced staged output ----
    int base = baseN + blockIdx.x * BLOCKB;
    int npts = N - base;
    if (npts >= BLOCKB) {
        const float4* s4 = (const float4*)sOut;
        float4* o4 = (float4*)(out + (size_t)base * 39);
        #pragma unroll 4
        for (int i = tid; i < (BLOCKB * 39) / 4; i += BLOCKB)
            o4[i] = s4[i];
    } else if (npts > 0) {
        for (int i = tid; i < npts * 39; i += BLOCKB)
            out[(size_t)base * 39 + i] = sOut[i];
    }
}

extern "C" void kernel_launch(void* const* d_in, const int* in_sizes, int n_in,
                              void* d_out, int out_size)
{
    const float* pos   = (const float*)d_in[0];
    const float* rx    = (const float*)d_in[1];
    const float* table = (const float*)d_in[2];
    const float* W1    = (const float*)d_in[3];
    const float* W2    = (const float*)d_in[4];
    const float* aabb  = (const float*)d_in[5];
    const int*   degp  = (n_in > 6) ? (const int*)d_in[6] : nullptr;

    int N = in_sizes[0] / 3;

    // one-time stream/event creation (host-side only; happens on the first,
    // non-captured correctness call)
    static cudaStream_t strA = nullptr, strB = nullptr;
    static cudaEvent_t evRoot = nullptr, evDone = nullptr;
    static cudaEvent_t evA[MAXCHUNKS], evB[MAXCHUNKS];
    if (!strA) {
        cudaStreamCreateWithFlags(&strA, cudaStreamNonBlocking);
        cudaStreamCreateWithFlags(&strB, cudaStreamNonBlocking);
        cudaEventCreateWithFlags(&evRoot, cudaEventDisableTiming);
        cudaEventCreateWithFlags(&evDone, cudaEventDisableTiming);
        for (int i = 0; i < MAXCHUNKS; i++) {
            cudaEventCreateWithFlags(&evA[i], cudaEventDisableTiming);
            cudaEventCreateWithFlags(&evB[i], cudaEventDisableTiming);
        }
    }

    // fork both worker streams from the caller's (default) stream
    cudaEventRecord(evRoot, 0);
    cudaStreamWaitEvent(strA, evRoot, 0);
    cudaStreamWaitEvent(strB, evRoot, 0);

    // upload weights to constant memory on stream B (B is the only consumer)
    cudaMemcpyToSymbolAsync(cW1, W1, 1024 * sizeof(float), 0,
                            cudaMemcpyDeviceToDevice, strB);
    cudaMemcpyToSymbolAsync(cW2, W2, 1024 * sizeof(float), 0,
                            cudaMemcpyDeviceToDevice, strB);

    int nchunks = (N + CH - 1) / CH;
    if (nchunks > MAXCHUNKS) nchunks = MAXCHUNKS;

    for (int i = 0; i < nchunks; i++) {
        int base = i * CH;
        int chunk = (N - base < CH) ? (N - base) : CH;
        int buf = i & 1;
        // WAR guard: before A rewrites buffer `buf`, B_{i-2} must be done
        if (i >= 2)
            cudaStreamWaitEvent(strA, evB[i - 2], 0);
        dim3 gridA((chunk + BLOCKA * NPT - 1) / (BLOCKA * NPT), NLEV);
        ngp_encode_kernel<<<gridA, BLOCKA, 0, strA>>>(pos, table, aabb,
                                                      base, chunk, buf);
        cudaEventRecord(evA[i], strA);
        cudaStreamWaitEvent(strB, evA[i], 0);
        int gridB = (chunk + BLOCKB - 1) / BLOCKB;
        ngp_mlp_kernel<<<gridB, BLOCKB, 0, strB>>>(pos, rx, aabb, degp,
                                                   (float*)d_out, base, chunk,
                                                   N, buf);
        cudaEventRecord(evB[i], strB);
    }

    // rejoin into the caller's stream
    cudaEventRecord(evDone, strB);
    cudaStreamWaitEvent(0, evDone, 0);
}

// round 14
// speedup vs baseline: 1.2208x; 1.0214x over previous
#include <cuda_runtime.h>
#include <math.h>
#include <stdint.h>

#define TBITS 19
#define TSIZE (1u << TBITS)
#define TMASK (TSIZE - 1u)
#define NLEV 16
#define BLOCKA 256
#define NPT 2              // points per thread in kernel A
#define BLOCKB 128
#define CH 65536           // 4 chunks; double-buffered scratch
#define MAXCHUNKS 16

// double-buffered scratch: per (level l, slot k) a float2 plane of CH points
//   k=0: (F[2l], F[2l+1]) ; k=1: (Gx0,Gx1) ; k=2: (Gy0,Gy1) ; k=3: (Gz0,Gz1)
__device__ float2 g_scratch[2][64 * CH];

// weights in constant memory: FFMA takes c[bank][ofs] operand directly (no LDS)
__constant__ float cW1[1024];
__constant__ float cW2[1024];

// Dot2 building block: s/c = running twoSum accumulator, e = product-error sum.
__device__ __forceinline__ void dot2_term(float a, float b,
                                          float& s, float& c, float& e)
{
    float p = a * b;
    e += fmaf(a, b, -p);         // exact FMA product error
    float t = s + p;             // twoSum(s, p)
    float z = t - s;
    c += (s - (t - z)) + (p - z);
    s = t;
}

__device__ __forceinline__ float shY(int c, float x, float y, float z,
                                     float xx, float yy, float zz,
                                     float xy, float yz, float xz)
{
    switch (c) {
    case 0:  return 0.28209479177387814f;
    case 1:  return -0.4886025119029199f * y;
    case 2:  return  0.4886025119029199f * z;
    case 3:  return -0.4886025119029199f * x;
    case 4:  return  1.0925484305920792f * xy;
    case 5:  return -1.0925484305920792f * yz;
    case 6:  return  0.31539156525252005f * (2.f * zz - xx - yy);
    case 7:  return -1.0925484305920792f * xz;
    case 8:  return  0.5462742152960396f * (xx - yy);
    case 9:  return -0.5900435899266435f * y * (3.f * xx - yy);
    case 10: return  2.890611442640554f  * xy * z;
    case 11: return -0.4570457994644658f * y * (4.f * zz - xx - yy);
    case 12: return  0.3731763325901154f * z * (2.f * zz - 3.f * xx - 3.f * yy);
    case 13: return -0.4570457994644658f * x * (4.f * zz - xx - yy);
    case 14: return  1.445305721320277f  * z * (xx - yy);
    case 15: return -0.5900435899266435f * x * (xx - 3.f * yy);
    }
    return 0.f;
}

// ---------------- Kernel A: hash-grid gather, NPT points x 1 level per thread
__global__ __launch_bounds__(BLOCKA)
void ngp_encode_kernel(const float* __restrict__ pos,
                       const float* __restrict__ table,
                       const float* __restrict__ aabb,
                       int baseN, int chunk, int buf)
{
    __shared__ float sres;
    const int l = blockIdx.y;
    if (threadIdx.x == 0) {
        // Replicate reference: s = exp((ln(4096)-ln(16))/15); res_l = f32(16 * s^l)
        double s = exp(0.36967849629863747);
        sres = (float)(16.0 * pow(s, (double)l));
    }
    __syncthreads();

    const float res = sres;
    const float2* tab = ((const float2*)table) + (size_t)l * TSIZE;
    float2* S = g_scratch[buf];

    float a0 = aabb[0], a1 = aabb[1], a2 = aabb[2];
    float s0 = fmaxf(aabb[3] - a0, 1e-6f);
    float s1 = fmaxf(aabb[4] - a1, 1e-6f);
    float s2 = fmaxf(aabb[5] - a2, 1e-6f);

    const int base = blockIdx.x * (BLOCKA * NPT) + threadIdx.x;

    // per-point state
    int   np[NPT];
    float wxp[NPT], wyp[NPT], wzp[NPT];
    unsigned hx0p[NPT], hx1p[NPT], hy0p[NPT], hy1p[NPT], hz0p[NPT], hz1p[NPT];
    bool valid[NPT];

    // front-end for both points (independent chains interleave)
    #pragma unroll
    for (int p = 0; p < NPT; p++) {
        int n = base + p * BLOCKA;
        np[p] = n;
        valid[p] = (n < chunk);
        if (!valid[p]) continue;
        int ng = baseN + n;
        float P0 = pos[3 * ng + 0], P1 = pos[3 * ng + 1], P2 = pos[3 * ng + 2];
        float q0 = __fdiv_rn(P0 - a0, s0);
        float q1 = __fdiv_rn(P1 - a1, s1);
        float q2 = __fdiv_rn(P2 - a2, s2);
        float pn0 = fminf(fmaxf(q0, 0.f), 1.f);
        float pn1 = fminf(fmaxf(q1, 0.f), 1.f);
        float pn2 = fminf(fmaxf(q2, 0.f), 1.f);
        float px = pn0 * res, py = pn1 * res, pz = pn2 * res;
        float fx = floorf(px), fy = floorf(py), fz = floorf(pz);
        wxp[p] = px - fx; wyp[p] = py - fy; wzp[p] = pz - fz;
        unsigned ux = (unsigned)fx, uy = (unsigned)fy, uz = (unsigned)fz;
        hx0p[p] = ux;               hx1p[p] = ux + 1u;
        hy0p[p] = uy * 2654435761u; hy1p[p] = (uy + 1u) * 2654435761u;
        hz0p[p] = uz * 805459861u;  hz1p[p] = (uz + 1u) * 805459861u;
    }

    // batch ALL gathers for both points.
    // x-pair merge: PRIMES[0]==1, so for even ux the two x-corners of a
    // (y,z) pair live at adjacent table entries {g, g+1} -> one float4 load.
    float2 fv[NPT][8];   // fv[p][c], c = bx*4 + by*2 + bz
    #pragma unroll
    for (int p = 0; p < NPT; p++) {
        if (!valid[p]) continue;
        if ((hx0p[p] & 1u) == 0u) {
            #pragma unroll
            for (int q = 0; q < 4; q++) {
                const int by = q >> 1, bz = q & 1;
                unsigned hyz = (by ? hy1p[p] : hy0p[p]) ^
                               (bz ? hz1p[p] : hz0p[p]);
                unsigned h0 = (hx0p[p] ^ hyz) & TMASK;  // corner bx=0
                unsigned g = h0 & ~1u;                  // h1 = h0 ^ 1
                float4 v = __ldg((const float4*)(tab + g));
                if (h0 & 1u) {
                    fv[p][q]     = make_float2(v.z, v.w);  // bx=0 at g+1
                    fv[p][q + 4] = make_float2(v.x, v.y);  // bx=1 at g
                } else {
                    fv[p][q]     = make_float2(v.x, v.y);
                    fv[p][q + 4] = make_float2(v.z, v.w);
                }
            }
        } else {
            #pragma unroll
            for (int c = 0; c < 8; c++) {
                const int bx = (c >> 2) & 1, by = (c >> 1) & 1, bz = c & 1;
                unsigned hh = (bx ? hx1p[p] : hx0p[p]) ^
                              (by ? hy1p[p] : hy0p[p]) ^
                              (bz ? hz1p[p] : hz0p[p]);
                fv[p][c] = __ldg(&tab[hh & TMASK]);
            }
        }
    }

    // accumulate + store per point (identical fma order to R11/R13)
    #pragma unroll
    for (int p = 0; p < NPT; p++) {
        if (!valid[p]) continue;
        float wx = wxp[p], wy = wyp[p], wz = wzp[p];

        float f0a = 0.f, f0b = 0.f, f1a = 0.f, f1b = 0.f;
        float gx0a = 0.f, gx0b = 0.f, gx1a = 0.f, gx1b = 0.f;
        float gy0a = 0.f, gy0b = 0.f, gy1a = 0.f, gy1b = 0.f;
        float gz0a = 0.f, gz0b = 0.f, gz1a = 0.f, gz1b = 0.f;

        #pragma unroll
        for (int c = 0; c < 8; c++) {
            const int bx = (c >> 2) & 1, by = (c >> 1) & 1, bz = c & 1;
            float2 f = fv[p][c];
            float tx = bx ? wx : (1.f - wx);
            float ty = by ? wy : (1.f - wy);
            float tz = bz ? wz : (1.f - wz);
            float pyz = ty * tz;
            float pxz = tx * tz;
            float pxy = tx * ty;
            float wc  = tx * pyz;
            float sx = bx ? pyz : -pyz;
            float sy = by ? pxz : -pxz;
            float sz = bz ? pxy : -pxy;
            if (c & 1) {
                f0b = fmaf(f.x, wc, f0b);   f1b = fmaf(f.y, wc, f1b);
                gx0b = fmaf(f.x, sx, gx0b); gx1b = fmaf(f.y, sx, gx1b);
                gy0b = fmaf(f.x, sy, gy0b); gy1b = fmaf(f.y, sy, gy1b);
                gz0b = fmaf(f.x, sz, gz0b); gz1b = fmaf(f.y, sz, gz1b);
            } else {
                f0a = fmaf(f.x, wc, f0a);   f1a = fmaf(f.y, wc, f1a);
                gx0a = fmaf(f.x, sx, gx0a); gx1a = fmaf(f.y, sx, gx1a);
                gy0a = fmaf(f.x, sy, gy0a); gy1a = fmaf(f.y, sy, gy1a);
                gz0a = fmaf(f.x, sz, gz0a); gz1a = fmaf(f.y, sz, gz1a);
            }
        }

        int n = np[p];
        S[(size_t)(l * 4 + 0) * CH + n] = make_float2(f0a + f0b, f1a + f1b);
        S[(size_t)(l * 4 + 1) * CH + n] = make_float2((gx0a + gx0b) * res, (gx1a + gx1b) * res);
        S[(size_t)(l * 4 + 2) * CH + n] = make_float2((gy0a + gy0b) * res, (gy1a + gy1b) * res);
        S[(size_t)(l * 4 + 3) * CH + n] = make_float2((gz0a + gz0b) * res, (gz1a + gz1b) * res);
    }
}

// ---------------- Kernel B: MLP fwd + bwd + SH, const-mem weights ----
__global__ __launch_bounds__(BLOCKB, 5)
void ngp_mlp_kernel(const float* __restrict__ pos,
                    const float* __restrict__ rx,
                    const float* __restrict__ aabb,
                    const int*   __restrict__ degp,
                    float* __restrict__ out,
                    int baseN, int chunk, int N, int buf)
{
    __shared__ __align__(16) float sOut[BLOCKB * 39];

    const int tid = threadIdx.x;
    const int n = blockIdx.x * BLOCKB + tid;
    const int ng = baseN + n;
    const float C0f = 0.28209479177387814f;
    const float2* S = g_scratch[buf];

    if (n < chunk) {
        float P0 = pos[3 * ng + 0], P1 = pos[3 * ng + 1], P2 = pos[3 * ng + 2];
        float a0 = aabb[0], a1 = aabb[1], a2 = aabb[2];
        float s0 = fmaxf(aabb[3] - a0, 1e-6f);
        float s1 = fmaxf(aabb[4] - a1, 1e-6f);
        float s2 = fmaxf(aabb[5] - a2, 1e-6f);
        float q0 = __fdiv_rn(P0 - a0, s0);
        float q1 = __fdiv_rn(P1 - a1, s1);
        float q2 = __fdiv_rn(P2 - a2, s2);
        bool sel = (q0 >= 0.f) && (q0 <= 1.f) &&
                   (q1 >= 0.f) && (q1 <= 1.f) &&
                   (q2 >= 0.f) && (q2 <= 1.f);

        // ---- load F from scratch (coalesced float2) ----
        float F[32];
        #pragma unroll
        for (int l = 0; l < NLEV; l++) {
            float2 fl = __ldg(&S[(size_t)(l * 4 + 0) * CH + n]);
            F[2 * l] = fl.x; F[2 * l + 1] = fl.y;
        }

        // ---- MLP layer 1: h = relu(F @ W1), const-operand FFMA ----
        float h[32];
        #pragma unroll
        for (int j = 0; j < 32; j++) {
            float a0_ = 0.f, a1_ = 0.f, a2_ = 0.f, a3_ = 0.f;
            #pragma unroll
            for (int i = 0; i < 32; i += 4) {
                a0_ = fmaf(F[i],     cW1[(i)     * 32 + j], a0_);
                a1_ = fmaf(F[i + 1], cW1[(i + 1) * 32 + j], a1_);
                a2_ = fmaf(F[i + 2], cW1[(i + 2) * 32 + j], a2_);
                a3_ = fmaf(F[i + 3], cW1[(i + 3) * 32 + j], a3_);
            }
            h[j] = fmaxf((a0_ + a2_) + (a1_ + a3_), 0.f);
        }

        // ---- view direction + SH, layer 2 early (before backward) ----
        int deg = 3;
        if (degp) {
            int v = degp[0];
            if (v >= 0 && v <= 8) deg = v;
        }
        int nact = (deg + 1) * (deg + 1);
        float dx = rx[0] - P0, dy = rx[1] - P1, dz = rx[2] - P2;
        float dn = __fsqrt_rn(dx * dx + dy * dy + dz * dz);
        float dnc = fmaxf(dn, 1e-20f);
        float X = __fdiv_rn(dx, dnc), Y = __fdiv_rn(dy, dnc), Z = __fdiv_rn(dz, dnc);
        float xx = X * X, yy = Y * Y, zz = Z * Z;
        float xy = X * Y, yz = Y * Z, xz = X * Z;

        float* row = &sOut[tid * 39];
        float scat0 = 0.f, scat1 = 0.f;
        #pragma unroll
        for (int c = 0; c < 16; c++) {
            float v0a = 0.f, v0b = 0.f, v1a = 0.f, v1b = 0.f;
            #pragma unroll
            for (int j = 0; j < 32; j += 2) {
                v0a = fmaf(h[j],     cW2[(j)     * 32 + 2 * c],     v0a);
                v1a = fmaf(h[j],     cW2[(j)     * 32 + 2 * c + 1], v1a);
                v0b = fmaf(h[j + 1], cW2[(j + 1) * 32 + 2 * c],     v0b);
                v1b = fmaf(h[j + 1], cW2[(j + 1) * 32 + 2 * c + 1], v1b);
            }
            float v0 = v0a + v0b, v1 = v1a + v1b;
            float Yc = shY(c, X, Y, Z, xx, yy, zz, xy, yz, xz);
            if (c < nact) {
                scat0 = fmaf(Yc, v0, scat0);
                scat1 = fmaf(Yc, v1, scat1);
            }
            row[7 + 2 * c]     = sel ? v0 : 0.f;
            row[7 + 2 * c + 1] = sel ? v1 : 0.f;
        }
        row[2] = sel ? scat0 : 0.f;
        row[3] = sel ? scat1 : 0.f;

        // ---- dens: compensated f32 dot (Dot2 ~ fp64 accuracy, FFMA cost) ----
        float sd0 = 0.f, cd0 = 0.f, ed0 = 0.f;
        float sd1 = 0.f, cd1 = 0.f, ed1 = 0.f;
        #pragma unroll
        for (int j = 0; j < 32; j++) {
            dot2_term(h[j], cW2[j * 32 + 0], sd0, cd0, ed0);
            dot2_term(h[j], cW2[j * 32 + 1], sd1, cd1, ed1);
        }
        float dot0 = sd0 + (cd0 + ed0);
        float dot1 = sd1 + (cd1 + ed1);
        float dens0 = C0f * dot0, dens1 = C0f * dot1;
        row[0] = sel ? dens0 : 0.f;
        row[1] = sel ? dens1 : 0.f;

        // ---- backward: f32 div/sqrt (exact ops, no amplification) ----
        float rf = __fsqrt_rn(dens0 * dens0 + dens1 * dens1);
        float uf0 = 0.f, uf1 = 0.f;
        if (rf > 0.f) { uf0 = __fdiv_rn(dens0, rf); uf1 = __fdiv_rn(dens1, rf); }
        float cu0 = C0f * uf0, cu1 = C0f * uf1;

        float gj[32];
        #pragma unroll
        for (int j = 0; j < 32; j++) {
            float v = fmaf(cu0, cW2[j * 32 + 0], cu1 * cW2[j * 32 + 1]);
            gj[j] = (h[j] > 0.f) ? v : 0.f;
        }

        float df[32];
        #pragma unroll
        for (int i = 0; i < 32; i++) {
            float a0_ = 0.f, a1_ = 0.f, a2_ = 0.f, a3_ = 0.f;
            #pragma unroll
            for (int j = 0; j < 32; j += 4) {
                a0_ = fmaf(gj[j],     cW1[i * 32 + j],     a0_);
                a1_ = fmaf(gj[j + 1], cW1[i * 32 + j + 1], a1_);
                a2_ = fmaf(gj[j + 2], cW1[i * 32 + j + 2], a2_);
                a3_ = fmaf(gj[j + 3], cW1[i * 32 + j + 3], a3_);
            }
            df[i] = (a0_ + a2_) + (a1_ + a3_);
        }

        // ---- final gradient reduction: Dot2 f32, then f32 normalize ----
        float sx = 0.f, cx = 0.f, ex = 0.f;
        float sy = 0.f, cy = 0.f, ey = 0.f;
        float sz = 0.f, cz = 0.f, ez = 0.f;
        #pragma unroll
        for (int l = 0; l < NLEV; l++) {
            float d0 = df[2 * l], d1 = df[2 * l + 1];
            float2 gx = __ldg(&S[(size_t)(l * 4 + 1) * CH + n]);
            float2 gy = __ldg(&S[(size_t)(l * 4 + 2) * CH + n]);
            float2 gz = __ldg(&S[(size_t)(l * 4 + 3) * CH + n]);
            dot2_term(d0, gx.x, sx, cx, ex);
            dot2_term(d1, gx.y, sx, cx, ex);
            dot2_term(d0, gy.x, sy, cy, ey);
            dot2_term(d1, gy.y, sy, cy, ey);
            dot2_term(d0, gz.x, sz, cz, ez);
            dot2_term(d1, gz.y, sz, cz, ez);
        }
        float gpx = sx + (cx + ex);
        float gpy = sy + (cy + ey);
        float gpz = sz + (cz + ez);

        float gw0 = __fdiv_rn(gpx, s0);
        float gw1 = __fdiv_rn(gpy, s1);
        float gw2 = __fdiv_rn(gpz, s2);
        float gn = __fsqrt_rn(gw0 * gw0 + gw1 * gw1 + gw2 * gw2);
        float gd = fmaxf(gn, 1e-20f);
        row[4] = sel ? __fdiv_rn(-gw0, gd) : 0.f;
        row[5] = sel ? __fdiv_rn(-gw1, gd) : 0.f;
        row[6] = sel ? __fdiv_rn(-gw2, gd) : 0.f;
    }

    __syncthreads();

    // ---- coalesced staged output ----
    int base = baseN + blockIdx.x * BLOCKB;
    int npts = N - base;
    if (npts >= BLOCKB) {
        const float4* s4 = (const float4*)sOut;
        float4* o4 = (float4*)(out + (size_t)base * 39);
        #pragma unroll 4
        for (int i = tid; i < (BLOCKB * 39) / 4; i += BLOCKB)
            o4[i] = s4[i];
    } else if (npts > 0) {
        for (int i = tid; i < npts * 39; i += BLOCKB)
            out[(size_t)base * 39 + i] = sOut[i];
    }
}

extern "C" void kernel_launch(void* const* d_in, const int* in_sizes, int n_in,
                              void* d_out, int out_size)
{
    const float* pos   = (const float*)d_in[0];
    const float* rx    = (const float*)d_in[1];
    const float* table = (const float*)d_in[2];
    const float* W1    = (const float*)d_in[3];
    const float* W2    = (const float*)d_in[4];
    const float* aabb  = (const float*)d_in[5];
    const int*   degp  = (n_in > 6) ? (const int*)d_in[6] : nullptr;

    int N = in_sizes[0] / 3;

    // one-time stream/event creation (host-side only; happens on the first,
    // non-captured correctness call)
    static cudaStream_t strA = nullptr, strB = nullptr;
    static cudaEvent_t evRoot = nullptr, evDone = nullptr;
    static cudaEvent_t evA[MAXCHUNKS], evB[MAXCHUNKS];
    if (!strA) {
        cudaStreamCreateWithFlags(&strA, cudaStreamNonBlocking);
        cudaStreamCreateWithFlags(&strB, cudaStreamNonBlocking);
        cudaEventCreateWithFlags(&evRoot, cudaEventDisableTiming);
        cudaEventCreateWithFlags(&evDone, cudaEventDisableTiming);
        for (int i = 0; i < MAXCHUNKS; i++) {
            cudaEventCreateWithFlags(&evA[i], cudaEventDisableTiming);
            cudaEventCreateWithFlags(&evB[i], cudaEventDisableTiming);
        }
    }

    // fork both worker streams from the caller's (default) stream
    cudaEventRecord(evRoot, 0);
    cudaStreamWaitEvent(strA, evRoot, 0);
    cudaStreamWaitEvent(strB, evRoot, 0);

    // upload weights to constant memory on stream B (B is the only consumer)
    cudaMemcpyToSymbolAsync(cW1, W1, 1024 * sizeof(float), 0,
                            cudaMemcpyDeviceToDevice, strB);
    cudaMemcpyToSymbolAsync(cW2, W2, 1024 * sizeof(float), 0,
                            cudaMemcpyDeviceToDevice, strB);

    int nchunks = (N + CH - 1) / CH;
    if (nchunks > MAXCHUNKS) nchunks = MAXCHUNKS;

    for (int i = 0; i < nchunks; i++) {
        int base = i * CH;
        int chunk = (N - base < CH) ? (N - base) : CH;
        int buf = i & 1;
        // WAR guard: before A rewrites buffer `buf`, B_{i-2} must be done
        if (i >= 2)
            cudaStreamWaitEvent(strA, evB[i - 2], 0);
        dim3 gridA((chunk + BLOCKA * NPT - 1) / (BLOCKA * NPT), NLEV);
        ngp_encode_kernel<<<gridA, BLOCKA, 0, strA>>>(pos, table, aabb,
                                                      base, chunk, buf);
        cudaEventRecord(evA[i], strA);
        cudaStreamWaitEvent(strB, evA[i], 0);
        int gridB = (chunk + BLOCKB - 1) / BLOCKB;
        ngp_mlp_kernel<<<gridB, BLOCKB, 0, strB>>>(pos, rx, aabb, degp,
                                                   (float*)d_out, base, chunk,
                                                   N, buf);
        cudaEventRecord(evB[i], strB);
    }

    // rejoin into the caller's stream
    cudaEventRecord(evDone, strB);
    cudaStreamWaitEvent(0, evDone, 0);
}